// round 17
// baseline (speedup 1.0000x reference)
#include <cuda_runtime.h>
#include <cuda_bf16.h>
#include <math.h>

#define Bn    8
#define Ln    2048
#define KSEL  64
#define EXCL  3
#define NAA   20
#define EMB   16
#define MD    7
#define D2CUT 144.0f      // r >= 12 -> smoothstep == 0 -> zero energy
#define BCAP  256         // bucket capacity before radix fallback
#define CANDN 1024        // flat candidate buffer per row
#define SEGC  128         // per-warp-window per-row segment capacity
#define BINSCALE (256.0f / 144.0f)

// Scratch (device globals: no allocation allowed)
__device__ float g_tab[NAA * NAA * MD];       // softplus(MLP(aa_i,aa_j))

// ---------------------------------------------------------------------------
// Kernel 0: exact fp32 MLP over 400 AA pairs -> 400x7 table. Also zeroes out.
// 2 pairs/block (ILP-2), 512 threads, 4-way K-split (short serial chains).
// ---------------------------------------------------------------------------
__global__ void __launch_bounds__(512) table_kernel(
    const float* __restrict__ emb,
    const float* __restrict__ W1, const float* __restrict__ b1,
    const float* __restrict__ W2, const float* __restrict__ b2,
    const float* __restrict__ W3, const float* __restrict__ b3,
    float* __restrict__ out)
{
    __shared__ float x[2][48];
    __shared__ float h1[2][128];
    __shared__ float h2[2][128];
    __shared__ float part[2][4][128];

    const int p0 = blockIdx.x * 2;
    const int tid = threadIdx.x;
    const int n = tid & 127;
    const int q4 = tid >> 7;            // 0..3

    if (blockIdx.x == 0 && tid < Bn) out[tid] = 0.f;   // stream-ordered zero

    if (tid < 2 * EMB) {
        int pr = tid >> 4, c = tid & 15;
        int p = p0 + pr;
        float ei = emb[(p / NAA) * EMB + c];
        float ej = emb[(p % NAA) * EMB + c];
        x[pr][c] = ei; x[pr][EMB + c] = ej; x[pr][2 * EMB + c] = ei * ej;
    }
    __syncthreads();

    {   // Layer 1: K=48, 4 x 12
        float a0 = 0.f, a1 = 0.f;
        const int k0 = q4 * 12;
        #pragma unroll
        for (int k = 0; k < 12; k++) {
            float w = W1[(k0 + k) * 128 + n];
            a0 = fmaf(x[0][k0 + k], w, a0);
            a1 = fmaf(x[1][k0 + k], w, a1);
        }
        part[0][q4][n] = a0; part[1][q4][n] = a1;
    }
    __syncthreads();
    if (q4 < 2)
        h1[q4][n] = fmaxf(b1[n] + part[q4][0][n] + part[q4][1][n]
                                + part[q4][2][n] + part[q4][3][n], 0.f);
    __syncthreads();

    {   // Layer 2: K=128, 4 x 32
        float a0 = 0.f, a1 = 0.f;
        const int k0 = q4 * 32;
        #pragma unroll
        for (int k = 0; k < 32; k++) {
            float w = W2[(k0 + k) * 128 + n];
            a0 = fmaf(h1[0][k0 + k], w, a0);
            a1 = fmaf(h1[1][k0 + k], w, a1);
        }
        part[0][q4][n] = a0; part[1][q4][n] = a1;
    }
    __syncthreads();
    if (q4 < 2)
        h2[q4][n] = fmaxf(b2[n] + part[q4][0][n] + part[q4][1][n]
                                + part[q4][2][n] + part[q4][3][n], 0.f);
    __syncthreads();

    if (tid < 2 * MD * 4) {   // Layer 3: K=128, 4 x 32, 7 outs x 2 pairs
        int pr = tid / 28, rem = tid % 28;
        int m = rem % MD, qq = rem / MD;
        float a = 0.f;
        const int k0 = qq * 32;
        #pragma unroll
        for (int k = 0; k < 32; k++)
            a = fmaf(h2[pr][k0 + k], W3[(k0 + k) * MD + m], a);
        part[pr][qq][m] = a;
    }
    __syncthreads();
    if (tid < 2 * MD) {
        int pr = tid / MD, m = tid % MD;
        float a = b3[m] + part[pr][0][m] + part[pr][1][m]
                        + part[pr][2][m] + part[pr][3][m];
        float sp = fmaxf(a, 0.f) + log1pf(expf(-fabsf(a)));  // jax softplus
        g_tab[(p0 + pr) * MD + m] = sp;
    }
}

// ---------------------------------------------------------------------------
// Per-pair energy: table lookup + anchored RBF product chain + smoothstep.
// ---------------------------------------------------------------------------
__device__ __forceinline__ float pair_energy(float d2, int jj,
                                             const int* __restrict__ seqb,
                                             int aa_base)
{
    float r = sqrtf(d2);
    int aj = __ldg(seqb + jj);
    const float* tp = g_tab + (aa_base + aj) * MD;
    const float C2  = 0.13533528323661270f;      // e^-2
    const float C6  = 2.4787521766663585e-3f;    // e^-6
    const float C10 = 4.5399929762484854e-5f;    // e^-10
    float t  = r - 8.f;
    float p3 = __expf(-2.f * t * t);
    float G  = __expf( 4.f * t);
    float Gi = __expf(-4.f * t);
    float p4 = p3 * G  * C2;
    float p5 = p4 * G  * C6;
    float p6 = p5 * G  * C10;
    float p2 = p3 * Gi * C2;
    float p1 = p2 * Gi * C6;
    float p0 = p1 * Gi * C10;
    float att = tp[0] * p0 + tp[1] * p1 + tp[2] * p2 + tp[3] * p3
              + tp[4] * p4 + tp[5] * p5 + tp[6] * p6;
    float tt = fminf(fmaxf((r - 10.f) * 0.5f, 0.f), 1.f);
    float sw = 1.f - tt * tt * (3.f - 2.f * tt);
    return -att * sw;
}

// ---------------------------------------------------------------------------
// Warp-0 radix digit resolution over a 256-bin histogram (8 bins/lane).
// ---------------------------------------------------------------------------
__device__ __forceinline__ void resolve8(const int* __restrict__ hist,
                                         unsigned long long* s_pref,
                                         int* s_targ, int shift, int tid)
{
    if (tid < 32) {
        const int base = tid * 8;
        int c8[8]; int ssum = 0;
        #pragma unroll
        for (int t = 0; t < 8; t++) { c8[t] = hist[base + t]; ssum += c8[t]; }
        int incl = ssum;
        #pragma unroll
        for (int o = 1; o < 32; o <<= 1) {
            int t = __shfl_up_sync(0xffffffffu, incl, o);
            if (tid >= o) incl += t;
        }
        int excl = incl - ssum;
        const int tgt = *s_targ;
        const unsigned long long pref = *s_pref;
        __syncwarp();
        int run = excl;
        #pragma unroll
        for (int t = 0; t < 8; t++) {
            if (run < tgt && tgt <= run + c8[t]) {
                *s_pref = pref | ((unsigned long long)(base + t) << shift);
                *s_targ = tgt - run;
            }
            run += c8[t];
        }
    }
}

// ---------------------------------------------------------------------------
// Kernel 1: TWO rows per CTA sharing the scan loads. R13 flat select per row.
// __launch_bounds__(256, 8) pins 8 CTAs/SM. key = (bits(d2) << 11) | j.
// Per-window cap 128 with a storage-free exact radix fallback (never taken).
// Final: one atomicAdd per CTA into out[b].
// ---------------------------------------------------------------------------
__global__ void __launch_bounds__(256, 8) topk_energy_kernel(
    const float* __restrict__ R, const int* __restrict__ seq,
    float* __restrict__ out)
{
    __shared__ unsigned long long seg[2 * 8 * SEGC];   // 16 KB (2 rows)
    __shared__ unsigned long long cand[CANDN];         // 8 KB
    __shared__ unsigned long long buf[BCAP];           // 2 KB
    __shared__ int hist[256];
    __shared__ int s_cnt[16];                          // [row*8 + warp]
    __shared__ int wtot[8];
    __shared__ float wsum[8];
    __shared__ int s_B, s_targ, s_bcnt;
    __shared__ unsigned long long s_T;
    __shared__ unsigned long long s_pref;

    const int tid = threadIdx.x;
    const int w = tid >> 5, lane = tid & 31;
    const unsigned lanelt = (1u << lane) - 1u;
    const int b = blockIdx.x >> 10;
    const int ipair = (blockIdx.x & 1023) << 1;        // rows ipair, ipair+1
    const float* __restrict__ Rb = R + (size_t)b * Ln * 3;
    const int* __restrict__ seqb = seq + b * Ln;

    const float x0 = Rb[3 * ipair],     y0 = Rb[3 * ipair + 1], z0 = Rb[3 * ipair + 2];
    const float x1 = Rb[3 * ipair + 3], y1 = Rb[3 * ipair + 4], z1 = Rb[3 * ipair + 5];

    // --- Scan: warp w owns j in [256w, 256w+256); both rows share loads ---
    int cnt0 = 0, cnt1 = 0;
    #pragma unroll
    for (int it = 0; it < 8; it++) {
        const int j = (w << 8) + (it << 5) + lane;
        const float xj = Rb[3 * j], yj = Rb[3 * j + 1], zj = Rb[3 * j + 2];

        float dx = x0 - xj, dy = y0 - yj, dz = z0 - zj;
        float d20 = fmaf(dx, dx, fmaf(dy, dy, fmaf(dz, dz, 1e-12f)));
        dx = x1 - xj; dy = y1 - yj; dz = z1 - zj;
        float d21 = fmaf(dx, dx, fmaf(dy, dy, fmaf(dz, dz, 1e-12f)));

        bool p0 = (d20 < D2CUT) && ((unsigned)(j - ipair + EXCL) > 2u * EXCL);
        unsigned m0 = __ballot_sync(0xffffffffu, p0);
        if (p0) {
            int pos = cnt0 + __popc(m0 & lanelt);
            if (pos < SEGC)
                seg[(w << 7) + pos] =
                    (((unsigned long long)__float_as_uint(d20)) << 11) | (unsigned)j;
        }
        cnt0 += __popc(m0);

        bool p1 = (d21 < D2CUT) && ((unsigned)(j - ipair - 1 + EXCL) > 2u * EXCL);
        unsigned m1 = __ballot_sync(0xffffffffu, p1);
        if (p1) {
            int pos = cnt1 + __popc(m1 & lanelt);
            if (pos < SEGC)
                seg[8 * SEGC + (w << 7) + pos] =
                    (((unsigned long long)__float_as_uint(d21)) << 11) | (unsigned)j;
        }
        cnt1 += __popc(m1);
    }
    if (lane == 0) { s_cnt[w] = cnt0; s_cnt[8 + w] = cnt1; }
    __syncthreads();

    float local = 0.f;

    #pragma unroll 1
    for (int r = 0; r < 2; r++) {
        const int i = ipair + r;
        const int aa_base = __ldg(seqb + i) * NAA;
        float rloc = 0.f;

        int ctot = 0; int ovf = 0;
        #pragma unroll
        for (int s = 0; s < 8; s++) {
            int c = s_cnt[r * 8 + s];
            ctot += c;
            ovf |= (c > SEGC);
        }

        if (!ovf && ctot <= CANDN) {
            // ===================== FLAT FAST PATH =====================
            {
                int off = 0;
                #pragma unroll
                for (int s = 0; s < 8; s++) {
                    int cs = s_cnt[r * 8 + s];
                    if (tid < cs) cand[off + tid] = seg[r * 8 * SEGC + (s << 7) + tid];
                    off += cs;
                }
            }
            if (tid == 0) { s_bcnt = 0; s_T = ~0ull; }
            hist[tid] = 0;
            __syncthreads();

            if (ctot > KSEL) {
                // --- 1-round 256-bin linear-d2 histogram ---
                for (int g = tid; g < ctot; g += 256) {
                    float d2 = __uint_as_float((unsigned)(cand[g] >> 11));
                    atomicAdd(&hist[min((int)(d2 * BINSCALE), 255)], 1);
                }
                __syncthreads();

                // --- Block inclusive scan over bins, find crossing bin ---
                int v = hist[tid];
                int incl = v;
                #pragma unroll
                for (int o = 1; o < 32; o <<= 1) {
                    int t = __shfl_up_sync(0xffffffffu, incl, o);
                    if (lane >= o) incl += t;
                }
                if (lane == 31) wtot[w] = incl;
                __syncthreads();
                if (tid == 0) {
                    int rr = 0;
                    #pragma unroll
                    for (int q = 0; q < 8; q++) { int t = wtot[q]; wtot[q] = rr; rr += t; }
                }
                __syncthreads();
                incl += wtot[w];
                int excl = incl - v;
                if (excl < KSEL && KSEL <= incl) { s_B = tid; s_targ = KSEL - excl; }
                __syncthreads();
                const int B = s_B;

                // --- Gather bucket + fused below-bucket energy ---
                for (int g = tid; g < ctot; g += 256) {
                    unsigned long long key = cand[g];
                    float d2 = __uint_as_float((unsigned)(key >> 11));
                    int bin = min((int)(d2 * BINSCALE), 255);
                    if (bin < B) {
                        rloc += pair_energy(d2, (int)(key & 2047ull), seqb, aa_base);
                    } else if (bin == B) {
                        int pos = atomicAdd(&s_bcnt, 1);
                        if (pos < BCAP) buf[pos] = key;
                    }
                }
                __syncthreads();
                const int bc = s_bcnt;

                if (bc <= BCAP) {
                    // --- Exact threshold by warp-0 rank count (unique keys) ---
                    if (tid < 32) {
                        const int tg = s_targ;
                        for (int c = lane; c < bc; c += 32) {
                            unsigned long long key = buf[c];
                            int rank = 0;
                            for (int t = 0; t < bc; t++) rank += (buf[t] < key);
                            if (rank == tg - 1) s_T = key;
                        }
                    }
                    __syncthreads();
                    const unsigned long long T = s_T;
                    for (int g = tid; g < bc; g += 256) {
                        unsigned long long key = buf[g];
                        if (key <= T) {
                            float d2 = __uint_as_float((unsigned)(key >> 11));
                            rloc += pair_energy(d2, (int)(key & 2047ull), seqb, aa_base);
                        }
                    }
                } else {
                    // --- Bucket overflow (never expected): exact flat radix ---
                    rloc = 0.f;
                    if (tid == 0) { s_pref = 0ull; s_targ = KSEL; }
                    __syncthreads();
                    for (int pass = 0; pass < 6; pass++) {
                        const int shift = 40 - 8 * pass;
                        hist[tid] = 0;
                        __syncthreads();
                        const unsigned long long hp = s_pref >> (shift + 8);
                        for (int g = tid; g < ctot; g += 256) {
                            unsigned long long key = cand[g];
                            if ((key >> (shift + 8)) == hp)
                                atomicAdd(&hist[(int)((key >> shift) & 255)], 1);
                        }
                        __syncthreads();
                        resolve8(hist, &s_pref, &s_targ, shift, tid);
                        __syncthreads();
                    }
                    const unsigned long long T = s_pref;
                    for (int g = tid; g < ctot; g += 256) {
                        unsigned long long key = cand[g];
                        if (key <= T) {
                            float d2 = __uint_as_float((unsigned)(key >> 11));
                            rloc += pair_energy(d2, (int)(key & 2047ull), seqb, aa_base);
                        }
                    }
                }
            } else {
                // ctot <= KSEL: every candidate contributes
                for (int g = tid; g < ctot; g += 256) {
                    unsigned long long key = cand[g];
                    float d2 = __uint_as_float((unsigned)(key >> 11));
                    rloc += pair_energy(d2, (int)(key & 2047ull), seqb, aa_base);
                }
            }
        } else {
            // ===== STORAGE-FREE EXACT FALLBACK (never expected) =====
            const float xi = Rb[3 * i], yi = Rb[3 * i + 1], zi = Rb[3 * i + 2];
            unsigned long long T = ~0ull;
            if (ctot > KSEL) {
                if (tid == 0) { s_pref = 0ull; s_targ = KSEL; }
                __syncthreads();
                for (int pass = 0; pass < 6; pass++) {
                    const int shift = 40 - 8 * pass;
                    hist[tid] = 0;
                    __syncthreads();
                    const unsigned long long hp = s_pref >> (shift + 8);
                    for (int j = tid; j < Ln; j += 256) {
                        float dx = xi - Rb[3 * j];
                        float dy = yi - Rb[3 * j + 1];
                        float dz = zi - Rb[3 * j + 2];
                        float d2 = fmaf(dx, dx, fmaf(dy, dy, fmaf(dz, dz, 1e-12f)));
                        if (d2 < D2CUT && (unsigned)(j - i + EXCL) > 2u * EXCL) {
                            unsigned long long key =
                                (((unsigned long long)__float_as_uint(d2)) << 11)
                                | (unsigned)j;
                            if ((key >> (shift + 8)) == hp)
                                atomicAdd(&hist[(int)((key >> shift) & 255)], 1);
                        }
                    }
                    __syncthreads();
                    resolve8(hist, &s_pref, &s_targ, shift, tid);
                    __syncthreads();
                }
                T = s_pref;
            }
            for (int j = tid; j < Ln; j += 256) {
                float dx = xi - Rb[3 * j];
                float dy = yi - Rb[3 * j + 1];
                float dz = zi - Rb[3 * j + 2];
                float d2 = fmaf(dx, dx, fmaf(dy, dy, fmaf(dz, dz, 1e-12f)));
                if (d2 < D2CUT && (unsigned)(j - i + EXCL) > 2u * EXCL) {
                    unsigned long long key =
                        (((unsigned long long)__float_as_uint(d2)) << 11)
                        | (unsigned)j;
                    if (key <= T)
                        rloc += pair_energy(d2, j, seqb, aa_base);
                }
            }
        }

        local += rloc;
        __syncthreads();     // protect cand/buf/hist reuse across rows
    }

    // --- Deterministic block reduction, then one atomic per CTA ---
    #pragma unroll
    for (int o = 16; o > 0; o >>= 1)
        local += __shfl_down_sync(0xffffffffu, local, o);
    if (lane == 0) wsum[w] = local;
    __syncthreads();
    if (tid == 0) {
        float s = 0.f;
        #pragma unroll
        for (int q = 0; q < 8; q++) s += wsum[q];
        atomicAdd(out + b, s);
    }
}

// ---------------------------------------------------------------------------
extern "C" void kernel_launch(void* const* d_in, const int* in_sizes, int n_in,
                              void* d_out, int out_size)
{
    const float* R       = (const float*)d_in[0];
    const int*   seq     = (const int*)  d_in[1];
    const float* emb     = (const float*)d_in[2];
    const float* W1      = (const float*)d_in[3];
    const float* b1      = (const float*)d_in[4];
    const float* W2      = (const float*)d_in[5];
    const float* b2      = (const float*)d_in[6];
    const float* W3      = (const float*)d_in[7];
    const float* b3      = (const float*)d_in[8];
    float* out = (float*)d_out;

    table_kernel<<<NAA * NAA / 2, 512>>>(emb, W1, b1, W2, b2, W3, b3, out);
    topk_energy_kernel<<<Bn * Ln / 2, 256>>>(R, seq, out);
}